// round 1
// baseline (speedup 1.0000x reference)
#include <cuda_runtime.h>

#define B_    8
#define N_    2048
#define EMB_  256
#define INNER_ 64
#define KNN_  16
#define NPTS_ (B_*N_)
#define HP    66   // padded row stride for h/sim smem (bank-conflict avoidance)

// Scratch (device globals; no dynamic allocation allowed)
__device__ float g_qmk[NPTS_*INNER_];   // q - k per point
__device__ float g_v  [NPTS_*INNER_];   // v per point
__device__ int   g_idx[NPTS_*KNN_];     // flat neighbor indices (batch*N + j)

// ---------------------------------------------------------------------------
// qkv = x @ w_qkv ; store d = q-k and v.  16 rows per block, 192 threads.
// ---------------------------------------------------------------------------
__global__ __launch_bounds__(192) void qkv_kernel(
    const float* __restrict__ x, const float* __restrict__ w)
{
    __shared__ float sx[16*EMB_];     // 16 KB
    __shared__ float sq[16*192];      // 12 KB
    int r0 = blockIdx.x * 16;
    for (int e = threadIdx.x; e < 16*EMB_; e += 192)
        sx[e] = x[r0*EMB_ + e];
    __syncthreads();

    int col = threadIdx.x;   // 0..191
    float acc[16];
#pragma unroll
    for (int r = 0; r < 16; r++) acc[r] = 0.f;

#pragma unroll 4
    for (int kk = 0; kk < EMB_; kk += 2) {
        float w0 = w[kk*192 + col];
        float w1 = w[(kk+1)*192 + col];
#pragma unroll
        for (int r = 0; r < 16; r++) {
            float2 xv = *(const float2*)&sx[r*EMB_ + kk];
            acc[r] += xv.x * w0 + xv.y * w1;
        }
    }
#pragma unroll
    for (int r = 0; r < 16; r++) sq[r*192 + col] = acc[r];
    __syncthreads();

    for (int e = threadIdx.x; e < 16*INNER_; e += 192) {
        int r = e >> 6, c = e & 63;
        g_qmk[(r0+r)*INNER_ + c] = sq[r*192 + c] - sq[r*192 + 64 + c];
        g_v  [(r0+r)*INNER_ + c] = sq[r*192 + 128 + c];
    }
}

// ---------------------------------------------------------------------------
// kNN (k=16 smallest squared distances, includes self).  One thread per query
// point; full batch pos tile in smem.  64 blocks of 256 threads.
// ---------------------------------------------------------------------------
__global__ __launch_bounds__(256) void knn_kernel(const float* __restrict__ pos)
{
    __shared__ float sp[N_*3];   // 24 KB
    int batch = blockIdx.x >> 3;
    int chunk = blockIdx.x & 7;
    const float* pb = pos + batch*N_*3;
    for (int e = threadIdx.x; e < N_*3; e += 256) sp[e] = pb[e];
    __syncthreads();

    int qi = chunk*256 + threadIdx.x;     // local point in batch
    float px = sp[qi*3+0], py = sp[qi*3+1], pz = sp[qi*3+2];

    float bd[KNN_]; int bi[KNN_];
#pragma unroll
    for (int t = 0; t < KNN_; t++) { bd[t] = 3.4e38f; bi[t] = 0; }

    for (int j = 0; j < N_; j++) {
        float dx = sp[j*3+0]-px, dy = sp[j*3+1]-py, dz = sp[j*3+2]-pz;
        float d2 = dx*dx + dy*dy + dz*dz;
        if (d2 < bd[KNN_-1]) {
            float cd = d2; int ci = j;
#pragma unroll
            for (int t = 0; t < KNN_; t++) {
                if (cd < bd[t]) {
                    float td = bd[t]; bd[t] = cd; cd = td;
                    int   ti = bi[t]; bi[t] = ci; ci = ti;
                }
            }
        }
    }
    int base = (batch*N_ + qi)*KNN_;
#pragma unroll
    for (int t = 0; t < KNN_; t++) g_idx[base + t] = batch*N_ + bi[t];
}

// ---------------------------------------------------------------------------
// Fused per-pair pipeline.  4 points (64 pairs) per block, 256 threads.
// ---------------------------------------------------------------------------
// dynamic smem layout (floats):
//   sW2   [256*64]  w_att2
//   sT    [64*256]  t (and mid 64x64 before t)
//   sH    [64*HP]   h rows (then sim / attn, in place)
//   sVN   [64*64]   v_nn rows
//   sWP2  [64*64]   w_pos2
//   sRel  [64*4]    rel_pos per row
//   sAgg  [4*64]
//   sMisc [640]     wp1(192) bp1(64) bp2(64) ba1(256) ba2(64)
//   sNbr  [64] int
#define SMEM_FUSED_FLOATS (16384 + 16384 + 64*HP + 4096 + 4096 + 256 + 256 + 640 + 64)

__global__ __launch_bounds__(256, 1) void fused_kernel(
    const float* __restrict__ pos,
    const float* __restrict__ w_pos1, const float* __restrict__ b_pos1,
    const float* __restrict__ w_pos2, const float* __restrict__ b_pos2,
    const float* __restrict__ w_att1, const float* __restrict__ b_att1,
    const float* __restrict__ w_att2, const float* __restrict__ b_att2,
    const float* __restrict__ w_out,  const float* __restrict__ b_out,
    float* __restrict__ out)
{
    extern __shared__ float sm[];
    float* sW2  = sm;
    float* sT   = sW2  + 16384;
    float* sH   = sT   + 16384;
    float* sVN  = sH   + 64*HP;
    float* sWP2 = sVN  + 4096;
    float* sRel = sWP2 + 4096;
    float* sAgg = sRel + 256;
    float* sMsc = sAgg + 256;
    float* sWP1 = sMsc;          // 192
    float* sBp1 = sMsc + 192;    // 64
    float* sBp2 = sMsc + 256;    // 64
    float* sBa1 = sMsc + 320;    // 256
    float* sBa2 = sMsc + 576;    // 64
    int*   sNbr = (int*)(sMsc + 640);

    const int tid = threadIdx.x;
    const int gp0 = blockIdx.x * 4;

    // ---- Phase 0: load weights / neighbor rows ----
    for (int e = tid; e < 16384; e += 256) sW2[e]  = w_att2[e];
    for (int e = tid; e < 4096;  e += 256) sWP2[e] = w_pos2[e];
    if (tid < 192) sWP1[tid] = w_pos1[tid];
    if (tid < 64) {
        sBp1[tid] = b_pos1[tid];
        sBp2[tid] = b_pos2[tid];
        sBa2[tid] = b_att2[tid];
    }
    sBa1[tid] = b_att1[tid];
    if (tid < 64) {
        int pl = tid >> 4;
        int gp = gp0 + pl;
        int nbr = g_idx[gp*KNN_ + (tid & 15)];
        sNbr[tid] = nbr;
        sRel[tid*4+0] = pos[nbr*3+0] - pos[gp*3+0];
        sRel[tid*4+1] = pos[nbr*3+1] - pos[gp*3+1];
        sRel[tid*4+2] = pos[nbr*3+2] - pos[gp*3+2];
    }
    __syncthreads();

    // ---- Phase 1: mid = relu(rel @ wp1 + bp1), 64x64 into sT ----
#pragma unroll
    for (int it = 0; it < 16; it++) {
        int e = tid + it*256;
        int r = e >> 6, c = e & 63;
        float a = sRel[r*4+0]*sWP1[c] + sRel[r*4+1]*sWP1[64+c]
                + sRel[r*4+2]*sWP1[128+c] + sBp1[c];
        sT[e] = fmaxf(a, 0.f);
    }
    __syncthreads();

    // ---- Phase 2: rpe = mid @ wp2 + bp2;  h = qmk[nbr]+rpe;  vn = v[nbr]+rpe ----
#pragma unroll
    for (int it = 0; it < 16; it++) {
        int e = tid + it*256;
        int r = e >> 6, cc = e & 63;
        float a0 = 0.f, a1 = 0.f, a2 = 0.f, a3 = 0.f;
#pragma unroll 4
        for (int c = 0; c < 64; c += 4) {
            a0 += sT[r*64 + c+0] * sWP2[(c+0)*64 + cc];
            a1 += sT[r*64 + c+1] * sWP2[(c+1)*64 + cc];
            a2 += sT[r*64 + c+2] * sWP2[(c+2)*64 + cc];
            a3 += sT[r*64 + c+3] * sWP2[(c+3)*64 + cc];
        }
        float rpe = sBp2[cc] + (a0 + a1) + (a2 + a3);
        int nbr = sNbr[r];
        sH [r*HP + cc] = g_qmk[nbr*64 + cc] + rpe;
        sVN[r*64 + cc] = g_v  [nbr*64 + cc] + rpe;
    }
    __syncthreads();

    // ---- Phase 3: t = relu(h @ w_att1 + b_att1), col = tid (0..255) ----
    {
        float acc[64];
#pragma unroll
        for (int r = 0; r < 64; r++) acc[r] = 0.f;
#pragma unroll 2
        for (int k2 = 0; k2 < 64; k2 += 2) {
            float w0 = w_att1[k2*256 + tid];
            float w1 = w_att1[(k2+1)*256 + tid];
#pragma unroll
            for (int r = 0; r < 64; r++) {
                float2 hv = *(const float2*)&sH[r*HP + k2];
                acc[r] += hv.x * w0 + hv.y * w1;
            }
        }
        float bb = sBa1[tid];
#pragma unroll
        for (int r = 0; r < 64; r++)
            sT[r*256 + tid] = fmaxf(acc[r] + bb, 0.f);
    }
    __syncthreads();

    // ---- Phase 4: sim = t @ w_att2 + b_att2, into sH (reuse) ----
    {
        int cc = tid & 63;
        int rg = tid >> 6;     // 0..3 -> rows rg*16 .. rg*16+15
        float acc[16];
#pragma unroll
        for (int i = 0; i < 16; i++) acc[i] = 0.f;
        for (int c = 0; c < 256; c += 4) {
            float w0 = sW2[(c+0)*64 + cc];
            float w1 = sW2[(c+1)*64 + cc];
            float w2 = sW2[(c+2)*64 + cc];
            float w3 = sW2[(c+3)*64 + cc];
#pragma unroll
            for (int i = 0; i < 16; i++) {
                const float4 tv = *(const float4*)&sT[(rg*16 + i)*256 + c];
                acc[i] += tv.x*w0 + tv.y*w1 + tv.z*w2 + tv.w*w3;
            }
        }
        float bb = sBa2[cc];
#pragma unroll
        for (int i = 0; i < 16; i++)
            sH[(rg*16 + i)*HP + cc] = acc[i] + bb;
    }
    __syncthreads();

    // ---- Phase 5: softmax over 64 channels, per row, in place ----
    if (tid < 64) {
        float mx = -3.4e38f;
#pragma unroll 8
        for (int c = 0; c < 64; c++) mx = fmaxf(mx, sH[tid*HP + c]);
        float s = 0.f;
#pragma unroll 8
        for (int c = 0; c < 64; c++) {
            float e = __expf(sH[tid*HP + c] - mx);
            sH[tid*HP + c] = e;
            s += e;
        }
        float inv = 1.f / s;
#pragma unroll 8
        for (int c = 0; c < 64; c++) sH[tid*HP + c] *= inv;
    }
    __syncthreads();

    // ---- Phase 6: per-point channel norm over 16 neighbors + aggregate ----
    {
        int pl = tid >> 6, cc = tid & 63;
        float a[16];
        float s2 = 0.f;
#pragma unroll
        for (int j = 0; j < 16; j++) {
            a[j] = sH[(pl*16 + j)*HP + cc];
            s2 += a[j]*a[j];
        }
        float inv = 1.f / fmaxf(sqrtf(s2), 1e-12f);
        float agg = 0.f;
#pragma unroll
        for (int j = 0; j < 16; j++)
            agg += a[j] * sVN[(pl*16 + j)*64 + cc];
        sAgg[pl*64 + cc] = agg * inv;
    }
    __syncthreads();

    // ---- Phase 7: out = agg @ w_out + b_out ----
    {
        float acc[4];
        float bb = b_out[tid];
#pragma unroll
        for (int pl = 0; pl < 4; pl++) acc[pl] = bb;
#pragma unroll 4
        for (int c = 0; c < 64; c++) {
            float wv = w_out[c*256 + tid];
#pragma unroll
            for (int pl = 0; pl < 4; pl++)
                acc[pl] += sAgg[pl*64 + c] * wv;
        }
#pragma unroll
        for (int pl = 0; pl < 4; pl++)
            out[(gp0 + pl)*256 + tid] = acc[pl];
    }
}

// ---------------------------------------------------------------------------
extern "C" void kernel_launch(void* const* d_in, const int* in_sizes, int n_in,
                              void* d_out, int out_size)
{
    const float* x      = (const float*)d_in[0];
    const float* pos    = (const float*)d_in[1];
    const float* w_qkv  = (const float*)d_in[2];
    const float* w_pos1 = (const float*)d_in[3];
    const float* b_pos1 = (const float*)d_in[4];
    const float* w_pos2 = (const float*)d_in[5];
    const float* b_pos2 = (const float*)d_in[6];
    const float* w_att1 = (const float*)d_in[7];
    const float* b_att1 = (const float*)d_in[8];
    const float* w_att2 = (const float*)d_in[9];
    const float* b_att2 = (const float*)d_in[10];
    const float* w_out  = (const float*)d_in[11];
    const float* b_out  = (const float*)d_in[12];
    float* out = (float*)d_out;

    (void)in_sizes; (void)n_in; (void)out_size;

    const int smem_fused = SMEM_FUSED_FLOATS * 4;
    cudaFuncSetAttribute(fused_kernel,
                         cudaFuncAttributeMaxDynamicSharedMemorySize, smem_fused);

    qkv_kernel<<<NPTS_/16, 192>>>(x, w_qkv);
    knn_kernel<<<B_*8, 256>>>(pos);
    fused_kernel<<<NPTS_/4, 256, smem_fused>>>(
        pos, w_pos1, b_pos1, w_pos2, b_pos2,
        w_att1, b_att1, w_att2, b_att2, w_out, b_out, out);
}

// round 2
// speedup vs baseline: 1.2619x; 1.2619x over previous
#include <cuda_runtime.h>

#define B_    8
#define N_    2048
#define EMB_  256
#define INNER_ 64
#define KNN_  16
#define NPTS_ (B_*N_)
#define HP    68   // padded row stride (floats) for sH / sMid

typedef unsigned long long ull;

__device__ __forceinline__ ull pack2(float lo, float hi) {
    ull r; asm("mov.b64 %0, {%1,%2};" : "=l"(r) : "f"(lo), "f"(hi)); return r;
}
__device__ __forceinline__ float2 unpk2(ull v) {
    float2 r; asm("mov.b64 {%0,%1}, %2;" : "=f"(r.x), "=f"(r.y) : "l"(v)); return r;
}
#define FMA2(acc, a, b) asm("fma.rn.f32x2 %0, %1, %2, %0;" : "+l"(acc) : "l"(a), "l"(b))

// Scratch (device globals; no dynamic allocation allowed)
__device__ float g_qmk[NPTS_*INNER_];   // q - k per point
__device__ float g_v  [NPTS_*INNER_];   // v per point
__device__ int   g_idx[NPTS_*KNN_];     // flat neighbor indices (batch*N + j)

// ---------------------------------------------------------------------------
// qkv = x @ w_qkv ; store d = q-k and v.  16 rows per block, 192 threads.
// ---------------------------------------------------------------------------
__global__ __launch_bounds__(192) void qkv_kernel(
    const float* __restrict__ x, const float* __restrict__ w)
{
    __shared__ float sx[16*EMB_];     // 16 KB
    __shared__ float sq[16*192];      // 12 KB
    int r0 = blockIdx.x * 16;
    for (int e = threadIdx.x; e < 16*EMB_; e += 192)
        sx[e] = x[r0*EMB_ + e];
    __syncthreads();

    int col = threadIdx.x;   // 0..191
    float acc[16];
#pragma unroll
    for (int r = 0; r < 16; r++) acc[r] = 0.f;

#pragma unroll 4
    for (int kk = 0; kk < EMB_; kk += 2) {
        float w0 = w[kk*192 + col];
        float w1 = w[(kk+1)*192 + col];
#pragma unroll
        for (int r = 0; r < 16; r++) {
            float2 xv = *(const float2*)&sx[r*EMB_ + kk];
            acc[r] += xv.x * w0 + xv.y * w1;
        }
    }
#pragma unroll
    for (int r = 0; r < 16; r++) sq[r*192 + col] = acc[r];
    __syncthreads();

    for (int e = threadIdx.x; e < 16*INNER_; e += 192) {
        int r = e >> 6, c = e & 63;
        g_qmk[(r0+r)*INNER_ + c] = sq[r*192 + c] - sq[r*192 + 64 + c];
        g_v  [(r0+r)*INNER_ + c] = sq[r*192 + 128 + c];
    }
}

// ---------------------------------------------------------------------------
// kNN (k=16 smallest squared distances, includes self).
// ---------------------------------------------------------------------------
__global__ __launch_bounds__(256) void knn_kernel(const float* __restrict__ pos)
{
    __shared__ float sp[N_*3];   // 24 KB
    int batch = blockIdx.x >> 3;
    int chunk = blockIdx.x & 7;
    const float* pb = pos + batch*N_*3;
    for (int e = threadIdx.x; e < N_*3; e += 256) sp[e] = pb[e];
    __syncthreads();

    int qi = chunk*256 + threadIdx.x;     // local point in batch
    float px = sp[qi*3+0], py = sp[qi*3+1], pz = sp[qi*3+2];

    float bd[KNN_]; int bi[KNN_];
#pragma unroll
    for (int t = 0; t < KNN_; t++) { bd[t] = 3.4e38f; bi[t] = 0; }

    for (int j = 0; j < N_; j++) {
        float dx = sp[j*3+0]-px, dy = sp[j*3+1]-py, dz = sp[j*3+2]-pz;
        float d2 = dx*dx + dy*dy + dz*dz;
        if (d2 < bd[KNN_-1]) {
            float cd = d2; int ci = j;
#pragma unroll
            for (int t = 0; t < KNN_; t++) {
                if (cd < bd[t]) {
                    float td = bd[t]; bd[t] = cd; cd = td;
                    int   ti = bi[t]; bi[t] = ci; ci = ti;
                }
            }
        }
    }
    int base = (batch*N_ + qi)*KNN_;
#pragma unroll
    for (int t = 0; t < KNN_; t++) g_idx[base + t] = batch*N_ + bi[t];
}

// ---------------------------------------------------------------------------
// Fused per-pair pipeline.  4 points (64 pairs) per block, 512 threads.
// f32x2-packed GEMM phases.
// ---------------------------------------------------------------------------
// smem layout (float offsets, all even -> 8B alignment for ull loads):
//   sW2p [16384]  w_att2 row-pairs, float2[cp*64+cc] = {w2[2cp][cc], w2[2cp+1][cc]}
//   sT   [16384]  t (64x256 row-major); first 64*HP floats alias sMid
//   sH   [64*HP]  h rows (then sim/attn in place)
//   sVN  [4096]   v_nn rows
//   sWPp [4096]   w_pos2 row-pairs (float2[cp*64+cc])
//   sRel [256]  sAgg [256]  sWP1 [192]  sBp1/2 [64+64]  sBa1 [256]  sBa2 [64]
//   sNbr [64] int
#define SMEM_FUSED_FLOATS (16384 + 16384 + 64*HP + 4096 + 4096 + 256 + 256 + 192 + 64 + 64 + 256 + 64 + 64)

__global__ __launch_bounds__(512, 1) void fused_kernel(
    const float* __restrict__ pos,
    const float* __restrict__ w_pos1, const float* __restrict__ b_pos1,
    const float* __restrict__ w_pos2, const float* __restrict__ b_pos2,
    const float* __restrict__ w_att1, const float* __restrict__ b_att1,
    const float* __restrict__ w_att2, const float* __restrict__ b_att2,
    const float* __restrict__ w_out,  const float* __restrict__ b_out,
    float* __restrict__ out)
{
    extern __shared__ float sm[];
    float* sW2p = sm;                     // 16384
    float* sT   = sm + 16384;             // 16384 (first 64*HP floats = sMid)
    float* sH   = sm + 32768;             // 4352
    float* sVN  = sm + 32768 + 64*HP;     // 4096
    float* sWPp = sVN + 4096;             // 4096
    float* sRel = sWPp + 4096;            // 256
    float* sAgg = sRel + 256;             // 256
    float* sWP1 = sAgg + 256;             // 192
    float* sBp1 = sWP1 + 192;             // 64
    float* sBp2 = sBp1 + 64;              // 64
    float* sBa1 = sBp2 + 64;              // 256
    float* sBa2 = sBa1 + 256;             // 64
    int*   sNbr = (int*)(sBa2 + 64);      // 64

    const int tid = threadIdx.x;
    const int gp0 = blockIdx.x * 4;

    // ---- Phase 0: stage weights (pre-paired) + neighbor rel-pos ----
    for (int e = tid; e < 8192; e += 512) {
        int cp = e >> 6, cc = e & 63;
        ((float2*)sW2p)[e] = make_float2(w_att2[(2*cp)*64 + cc],
                                         w_att2[(2*cp+1)*64 + cc]);
    }
    for (int e = tid; e < 2048; e += 512) {
        int cp = e >> 6, cc = e & 63;
        ((float2*)sWPp)[e] = make_float2(w_pos2[(2*cp)*64 + cc],
                                         w_pos2[(2*cp+1)*64 + cc]);
    }
    if (tid < 192) sWP1[tid] = w_pos1[tid];
    if (tid < 64) {
        sBp1[tid] = b_pos1[tid];
        sBp2[tid] = b_pos2[tid];
        sBa2[tid] = b_att2[tid];
    }
    if (tid < 256) sBa1[tid] = b_att1[tid];
    if (tid < 64) {
        int pl = tid >> 4;
        int gp = gp0 + pl;
        int nbr = g_idx[gp*KNN_ + (tid & 15)];
        sNbr[tid] = nbr;
        sRel[tid*4+0] = pos[nbr*3+0] - pos[gp*3+0];
        sRel[tid*4+1] = pos[nbr*3+1] - pos[gp*3+1];
        sRel[tid*4+2] = pos[nbr*3+2] - pos[gp*3+2];
    }
    __syncthreads();

    // ---- Phase 1: mid = relu(rel @ wp1 + bp1), 64x64 into sMid (=sT, stride HP) ----
#pragma unroll
    for (int i = 0; i < 8; i++) {
        int e = tid + i*512;
        int r = e >> 6, c = e & 63;
        float a = sRel[r*4+0]*sWP1[c] + sRel[r*4+1]*sWP1[64+c]
                + sRel[r*4+2]*sWP1[128+c] + sBp1[c];
        sT[r*HP + c] = fmaxf(a, 0.f);
    }
    __syncthreads();

    // ---- Phase 2: rpe = mid @ wp2 + bp2;  h = qmk[nbr]+rpe; vn = v[nbr]+rpe ----
    {
        int cc = tid & 63, rg = tid >> 6;   // rg 0..7 -> 8 rows
        int r0 = rg * 8;
        ull acc[8];
#pragma unroll
        for (int rr = 0; rr < 8; rr++) acc[rr] = 0ull;
#pragma unroll 2
        for (int cp = 0; cp < 32; cp++) {
            ull wp = *(const ull*)&sWPp[(cp*64 + cc)*2];
#pragma unroll
            for (int rr = 0; rr < 8; rr++) {
                ull a = *(const ull*)&sT[(r0+rr)*HP + 2*cp];
                FMA2(acc[rr], a, wp);
            }
        }
#pragma unroll
        for (int rr = 0; rr < 8; rr++) {
            int r = r0 + rr;
            float2 s = unpk2(acc[rr]);
            float rpe = s.x + s.y + sBp2[cc];
            int nbr = sNbr[r];
            sH [r*HP + cc] = g_qmk[nbr*64 + cc] + rpe;
            sVN[r*64 + cc] = g_v  [nbr*64 + cc] + rpe;
        }
    }
    __syncthreads();

    // ---- Phase 3: t = relu(h @ w_att1 + b_att1) -> sT row-major (64x256) ----
    {
        int c  = tid & 255;
        int r0 = (tid >> 8) * 32;
        ull acc[32];
#pragma unroll
        for (int rr = 0; rr < 32; rr++) acc[rr] = 0ull;

        float w0 = w_att1[0*256 + c];
        float w1 = w_att1[1*256 + c];
        for (int kp = 0; kp < 32; kp++) {
            float nw0 = 0.f, nw1 = 0.f;
            if (kp < 31) {
                nw0 = w_att1[(2*kp+2)*256 + c];
                nw1 = w_att1[(2*kp+3)*256 + c];
            }
            ull wp = pack2(w0, w1);
#pragma unroll
            for (int rr = 0; rr < 32; rr++) {
                ull a = *(const ull*)&sH[(r0+rr)*HP + 2*kp];
                FMA2(acc[rr], a, wp);
            }
            w0 = nw0; w1 = nw1;
        }
        float bb = sBa1[c];
#pragma unroll
        for (int rr = 0; rr < 32; rr++) {
            float2 s = unpk2(acc[rr]);
            sT[(r0+rr)*256 + c] = fmaxf(s.x + s.y + bb, 0.f);
        }
    }
    __syncthreads();

    // ---- Phase 4: sim = t @ w_att2 + b_att2 -> sH ----
    {
        int cc = tid & 63, rg = tid >> 6;
        int r0 = rg * 8;
        ull acc[8];
#pragma unroll
        for (int rr = 0; rr < 8; rr++) acc[rr] = 0ull;
#pragma unroll 2
        for (int cp = 0; cp < 128; cp++) {
            ull wp = *(const ull*)&sW2p[(cp*64 + cc)*2];
#pragma unroll
            for (int rr = 0; rr < 8; rr++) {
                ull a = *(const ull*)&sT[(r0+rr)*256 + 2*cp];
                FMA2(acc[rr], a, wp);
            }
        }
        float bb = sBa2[cc];
#pragma unroll
        for (int rr = 0; rr < 8; rr++) {
            float2 s = unpk2(acc[rr]);
            sH[(r0+rr)*HP + cc] = s.x + s.y + bb;
        }
    }
    __syncthreads();

    // ---- Phase 5: softmax over 64 channels per row (4 threads/row + shfl) ----
    if (tid < 256) {
        int row = tid >> 2, q = tid & 3;
        float* hrow = &sH[row*HP + q*16];
        float mx = -3.4e38f;
#pragma unroll
        for (int i = 0; i < 16; i++) mx = fmaxf(mx, hrow[i]);
        mx = fmaxf(mx, __shfl_xor_sync(0xffffffffu, mx, 1));
        mx = fmaxf(mx, __shfl_xor_sync(0xffffffffu, mx, 2));
        float ev[16];
        float s = 0.f;
#pragma unroll
        for (int i = 0; i < 16; i++) { ev[i] = __expf(hrow[i] - mx); s += ev[i]; }
        s += __shfl_xor_sync(0xffffffffu, s, 1);
        s += __shfl_xor_sync(0xffffffffu, s, 2);
        float inv = 1.f / s;
#pragma unroll
        for (int i = 0; i < 16; i++) hrow[i] = ev[i] * inv;
    }
    __syncthreads();

    // ---- Phase 6: per-point channel norm over 16 neighbors + aggregate ----
    if (tid < 256) {
        int pl = tid >> 6, cc = tid & 63;
        float a[16];
        float s2 = 0.f;
#pragma unroll
        for (int j = 0; j < 16; j++) {
            a[j] = sH[(pl*16 + j)*HP + cc];
            s2 += a[j]*a[j];
        }
        float inv = 1.f / fmaxf(sqrtf(s2), 1e-12f);
        float agg = 0.f;
#pragma unroll
        for (int j = 0; j < 16; j++)
            agg += a[j] * sVN[(pl*16 + j)*64 + cc];
        sAgg[pl*64 + cc] = agg * inv;
    }
    __syncthreads();

    // ---- Phase 7: out = agg @ w_out + b_out (2 points per thread) ----
    {
        int colc = tid & 255, pg = tid >> 8;   // pg 0..1 -> points {2pg, 2pg+1}
        float bb = b_out[colc];
        float acc0 = bb, acc1 = bb;
#pragma unroll 4
        for (int c = 0; c < 64; c++) {
            float wv = w_out[c*256 + colc];
            acc0 += sAgg[(2*pg+0)*64 + c] * wv;
            acc1 += sAgg[(2*pg+1)*64 + c] * wv;
        }
        out[(gp0 + 2*pg + 0)*256 + colc] = acc0;
        out[(gp0 + 2*pg + 1)*256 + colc] = acc1;
    }
}

// ---------------------------------------------------------------------------
extern "C" void kernel_launch(void* const* d_in, const int* in_sizes, int n_in,
                              void* d_out, int out_size)
{
    const float* x      = (const float*)d_in[0];
    const float* pos    = (const float*)d_in[1];
    const float* w_qkv  = (const float*)d_in[2];
    const float* w_pos1 = (const float*)d_in[3];
    const float* b_pos1 = (const float*)d_in[4];
    const float* w_pos2 = (const float*)d_in[5];
    const float* b_pos2 = (const float*)d_in[6];
    const float* w_att1 = (const float*)d_in[7];
    const float* b_att1 = (const float*)d_in[8];
    const float* w_att2 = (const float*)d_in[9];
    const float* b_att2 = (const float*)d_in[10];
    const float* w_out  = (const float*)d_in[11];
    const float* b_out  = (const float*)d_in[12];
    float* out = (float*)d_out;

    (void)in_sizes; (void)n_in; (void)out_size;

    const int smem_fused = SMEM_FUSED_FLOATS * 4;
    cudaFuncSetAttribute(fused_kernel,
                         cudaFuncAttributeMaxDynamicSharedMemorySize, smem_fused);

    qkv_kernel<<<NPTS_/16, 192>>>(x, w_qkv);
    knn_kernel<<<B_*8, 256>>>(pos);
    fused_kernel<<<NPTS_/4, 512, smem_fused>>>(
        pos, w_pos1, b_pos1, w_pos2, b_pos2,
        w_att1, b_att1, w_att2, b_att2, w_out, b_out, out);
}

// round 3
// speedup vs baseline: 1.5626x; 1.2382x over previous
#include <cuda_runtime.h>

#define B_    8
#define N_    2048
#define EMB_  256
#define INNER_ 64
#define KNN_  16
#define NPTS_ (B_*N_)
#define MS    66    // mid row stride
#define HPD   68    // h/sim row stride
#define ST    258   // t row stride

typedef unsigned long long ull;

__device__ __forceinline__ float2 unpk2(ull v) {
    float2 r; asm("mov.b64 {%0,%1}, %2;" : "=f"(r.x), "=f"(r.y) : "l"(v)); return r;
}
#define FMA2(acc, a, b) asm("fma.rn.f32x2 %0, %1, %2, %0;" : "+l"(acc) : "l"(a), "l"(b))

// Scratch (device globals; no dynamic allocation allowed)
__device__ float g_qmk[NPTS_*INNER_];
__device__ float g_v  [NPTS_*INNER_];
__device__ int   g_idx[NPTS_*KNN_];
// pre-paired weights: pair p holds {w[2p][c], w[2p+1][c]}
__device__ __align__(16) float2 g_wqp[128*192];   // w_qkv
__device__ __align__(16) float2 g_w1p[32*256];    // w_att1
__device__ __align__(16) float2 g_w2p[128*64];    // w_att2
__device__ __align__(16) float2 g_wpp[32*64];     // w_pos2

// ---------------------------------------------------------------------------
__global__ __launch_bounds__(256) void prep_kernel(
    const float* __restrict__ wq, const float* __restrict__ w1,
    const float* __restrict__ w2, const float* __restrict__ wp)
{
    int i = blockIdx.x*256 + threadIdx.x;
    if (i < 24576) {
        int kp = i/192, c = i%192;
        g_wqp[i] = make_float2(wq[(2*kp)*192+c], wq[(2*kp+1)*192+c]);
    } else if (i < 32768) {
        int j = i - 24576; int kp = j>>8, c = j&255;
        g_w1p[j] = make_float2(w1[(2*kp)*256+c], w1[(2*kp+1)*256+c]);
    } else if (i < 40960) {
        int j = i - 32768; int kp = j>>6, c = j&63;
        g_w2p[j] = make_float2(w2[(2*kp)*64+c], w2[(2*kp+1)*64+c]);
    } else if (i < 43008) {
        int j = i - 40960; int kp = j>>6, c = j&63;
        g_wpp[j] = make_float2(wp[(2*kp)*64+c], wp[(2*kp+1)*64+c]);
    }
}

// ---------------------------------------------------------------------------
// qkv: 32 rows/block, 256 threads; thread tile = 8 rows x {q,k,v} of col cg.
// ---------------------------------------------------------------------------
__global__ __launch_bounds__(256) void qkv_kernel(const float* __restrict__ x)
{
    __shared__ float sx[32*EMB_];     // 32 KB
    int r0 = blockIdx.x * 32;
    {
        const float4* xin = (const float4*)(x + (size_t)r0*EMB_);
        float4* sx4 = (float4*)sx;
        for (int i = threadIdx.x; i < 2048; i += 256) sx4[i] = xin[i];
    }
    __syncthreads();

    int cg = threadIdx.x & 63, rg = threadIdx.x >> 6;   // rg 0..3 -> 8 rows
    ull acc[8][3];
#pragma unroll
    for (int rr = 0; rr < 8; rr++)
#pragma unroll
        for (int cc = 0; cc < 3; cc++) acc[rr][cc] = 0ull;

    ull wc[3], wn[3];
#pragma unroll
    for (int cc = 0; cc < 3; cc++)
        wc[cc] = *(const ull*)&g_wqp[cg + 64*cc];

    for (int kp = 0; kp < 128; kp++) {
        if (kp < 127) {
#pragma unroll
            for (int cc = 0; cc < 3; cc++)
                wn[cc] = *(const ull*)&g_wqp[(kp+1)*192 + cg + 64*cc];
        }
#pragma unroll
        for (int rr = 0; rr < 8; rr++) {
            ull a = *(const ull*)&sx[(rg*8+rr)*EMB_ + 2*kp];
            FMA2(acc[rr][0], a, wc[0]);
            FMA2(acc[rr][1], a, wc[1]);
            FMA2(acc[rr][2], a, wc[2]);
        }
#pragma unroll
        for (int cc = 0; cc < 3; cc++) wc[cc] = wn[cc];
    }
#pragma unroll
    for (int rr = 0; rr < 8; rr++) {
        float2 sq = unpk2(acc[rr][0]);
        float2 sk = unpk2(acc[rr][1]);
        float2 sv = unpk2(acc[rr][2]);
        int row = r0 + rg*8 + rr;
        g_qmk[row*64 + cg] = (sq.x + sq.y) - (sk.x + sk.y);
        g_v  [row*64 + cg] = sv.x + sv.y;
    }
}

// ---------------------------------------------------------------------------
// kNN (k=16 smallest squared distances, includes self).
// ---------------------------------------------------------------------------
__global__ __launch_bounds__(256) void knn_kernel(const float* __restrict__ pos)
{
    __shared__ float sp[N_*3];   // 24 KB
    int batch = blockIdx.x >> 3;
    int chunk = blockIdx.x & 7;
    const float* pb = pos + batch*N_*3;
    for (int e = threadIdx.x; e < N_*3; e += 256) sp[e] = pb[e];
    __syncthreads();

    int qi = chunk*256 + threadIdx.x;
    float px = sp[qi*3+0], py = sp[qi*3+1], pz = sp[qi*3+2];

    float bd[KNN_]; int bi[KNN_];
#pragma unroll
    for (int t = 0; t < KNN_; t++) { bd[t] = 3.4e38f; bi[t] = 0; }

    for (int j = 0; j < N_; j++) {
        float dx = sp[j*3+0]-px, dy = sp[j*3+1]-py, dz = sp[j*3+2]-pz;
        float d2 = dx*dx + dy*dy + dz*dz;
        if (d2 < bd[KNN_-1]) {
            float cd = d2; int ci = j;
#pragma unroll
            for (int t = 0; t < KNN_; t++) {
                if (cd < bd[t]) {
                    float td = bd[t]; bd[t] = cd; cd = td;
                    int   ti = bi[t]; bi[t] = ci; ci = ti;
                }
            }
        }
    }
    int base = (batch*N_ + qi)*KNN_;
#pragma unroll
    for (int t = 0; t < KNN_; t++) g_idx[base + t] = batch*N_ + bi[t];
}

// ---------------------------------------------------------------------------
// Fused kernel: 4 points (64 pairs) per block, 512 threads, register-tiled.
// ---------------------------------------------------------------------------
#define SMEM_FUSED_FLOATS 46656

__global__ __launch_bounds__(512, 1) void fused_kernel(
    const float* __restrict__ pos,
    const float* __restrict__ w_pos1, const float* __restrict__ b_pos1,
    const float* __restrict__ b_pos2,
    const float* __restrict__ b_att1, const float* __restrict__ b_att2,
    const float* __restrict__ w_out,  const float* __restrict__ b_out,
    float* __restrict__ out)
{
    extern __shared__ float sm[];
    float* sW2p = sm;                    // 16384 (float2[kp*64+col] pairs)
    float* sT   = sm + 16384;            // 16512: mid(stride 66) -> t(stride 258) -> partials(16384)
    float* sH   = sm + 32896;            // 4352 (stride 68)
    float* sVN  = sm + 37248;            // 4096
    float* sWPp = sm + 41344;            // 4096 (float2 pairs)
    float* sRel = sm + 45440;            // 256
    float* sAgg = sRel + 256;            // 256
    float* sWP1 = sAgg + 256;            // 192
    float* sBp1 = sWP1 + 192;            // 64
    float* sBp2 = sBp1 + 64;             // 64
    float* sBa1 = sBp2 + 64;             // 256
    float* sBa2 = sBa1 + 256;            // 64
    int*   sNbr = (int*)(sBa2 + 64);     // 64

    const int tid = threadIdx.x;
    const int gp0 = blockIdx.x * 4;

    // ---- Phase 0: stage weights + neighbor rel-pos ----
    {
        float4* dst = (float4*)sW2p; const float4* src = (const float4*)g_w2p;
        for (int i = tid; i < 4096; i += 512) dst[i] = src[i];
        float4* d2 = (float4*)sWPp;  const float4* s2 = (const float4*)g_wpp;
        for (int i = tid; i < 1024; i += 512) d2[i] = s2[i];
    }
    if (tid < 192) sWP1[tid] = w_pos1[tid];
    if (tid < 64) {
        sBp1[tid] = b_pos1[tid];
        sBp2[tid] = b_pos2[tid];
        sBa2[tid] = b_att2[tid];
    }
    if (tid >= 64 && tid < 320) sBa1[tid-64] = b_att1[tid-64];
    if (tid < 64) {
        int pl = tid >> 4;
        int gp = gp0 + pl;
        int nbr = g_idx[gp*KNN_ + (tid & 15)];
        sNbr[tid] = nbr;
        sRel[tid*4+0] = pos[nbr*3+0] - pos[gp*3+0];
        sRel[tid*4+1] = pos[nbr*3+1] - pos[gp*3+1];
        sRel[tid*4+2] = pos[nbr*3+2] - pos[gp*3+2];
    }
    __syncthreads();

    // ---- Phase 1: mid = relu(rel @ wp1 + bp1) -> sT stride MS ----
#pragma unroll
    for (int i = 0; i < 8; i++) {
        int e = tid + i*512;
        int r = e >> 6, c = e & 63;
        float a = sRel[r*4+0]*sWP1[c] + sRel[r*4+1]*sWP1[64+c]
                + sRel[r*4+2]*sWP1[128+c] + sBp1[c];
        sT[r*MS + c] = fmaxf(a, 0.f);
    }
    __syncthreads();

    // ---- Phase 2: rpe = mid @ wp2 + bp2; h = qmk[nbr]+rpe; vn = v[nbr]+rpe ----
    {
        int cg = tid & 31, rg = tid >> 5;   // rg 0..15 -> 4 rows
        int r0v = rg * 4;
        ull acc[4][2];
#pragma unroll
        for (int rr = 0; rr < 4; rr++) { acc[rr][0] = 0ull; acc[rr][1] = 0ull; }
#pragma unroll 4
        for (int kp = 0; kp < 32; kp++) {
            ull w0 = *(const ull*)&sWPp[(kp*64 + cg)*2];
            ull w1 = *(const ull*)&sWPp[(kp*64 + cg + 32)*2];
#pragma unroll
            for (int rr = 0; rr < 4; rr++) {
                ull a = *(const ull*)&sT[(r0v+rr)*MS + 2*kp];
                FMA2(acc[rr][0], a, w0);
                FMA2(acc[rr][1], a, w1);
            }
        }
#pragma unroll
        for (int rr = 0; rr < 4; rr++) {
            int r = r0v + rr;
            int nbr = sNbr[r];
#pragma unroll
            for (int cc = 0; cc < 2; cc++) {
                int col = cg + 32*cc;
                float2 s = unpk2(acc[rr][cc]);
                float rpe = s.x + s.y + sBp2[col];
                sH [r*HPD + col] = g_qmk[nbr*64 + col] + rpe;
                sVN[r*64  + col] = g_v  [nbr*64 + col] + rpe;
            }
        }
    }
    __syncthreads();

    // ---- Phase 3: t = relu(h @ w_att1 + b_att1) -> sT stride ST ----
    {
        int cg = tid & 63, rg = tid >> 6;   // rg 0..7 -> 8 rows
        int r0v = rg * 8;
        ull acc[8][4];
#pragma unroll
        for (int rr = 0; rr < 8; rr++)
#pragma unroll
            for (int cc = 0; cc < 4; cc++) acc[rr][cc] = 0ull;

        ull wc[4], wn[4];
#pragma unroll
        for (int cc = 0; cc < 4; cc++)
            wc[cc] = *(const ull*)&g_w1p[cg + 64*cc];

        for (int kp = 0; kp < 32; kp++) {
            if (kp < 31) {
#pragma unroll
                for (int cc = 0; cc < 4; cc++)
                    wn[cc] = *(const ull*)&g_w1p[(kp+1)*256 + cg + 64*cc];
            }
#pragma unroll
            for (int rr = 0; rr < 8; rr++) {
                ull a = *(const ull*)&sH[(r0v+rr)*HPD + 2*kp];
                FMA2(acc[rr][0], a, wc[0]);
                FMA2(acc[rr][1], a, wc[1]);
                FMA2(acc[rr][2], a, wc[2]);
                FMA2(acc[rr][3], a, wc[3]);
            }
#pragma unroll
            for (int cc = 0; cc < 4; cc++) wc[cc] = wn[cc];
        }
#pragma unroll
        for (int rr = 0; rr < 8; rr++)
#pragma unroll
            for (int cc = 0; cc < 4; cc++) {
                int col = cg + 64*cc;
                float2 s = unpk2(acc[rr][cc]);
                sT[(r0v+rr)*ST + col] = fmaxf(s.x + s.y + sBa1[col], 0.f);
            }
    }
    __syncthreads();

    // ---- Phase 4: sim = t @ w_att2 + b_att2 (split-K x4) -> sH ----
    {
        int sp = tid >> 7;                 // 0..3 k-split
        int t  = tid & 127;
        int cg = t & 15, rg = t >> 4;      // rg 0..7 -> 8 rows
        int r0v = rg * 8;
        ull acc[8][4];
#pragma unroll
        for (int rr = 0; rr < 8; rr++)
#pragma unroll
            for (int cc = 0; cc < 4; cc++) acc[rr][cc] = 0ull;

        int kbase = sp * 32;
#pragma unroll 2
        for (int j = 0; j < 32; j++) {
            int kp = kbase + j;
            ull w0 = *(const ull*)&sW2p[(kp*64 + cg     )*2];
            ull w1 = *(const ull*)&sW2p[(kp*64 + cg + 16)*2];
            ull w2 = *(const ull*)&sW2p[(kp*64 + cg + 32)*2];
            ull w3 = *(const ull*)&sW2p[(kp*64 + cg + 48)*2];
#pragma unroll
            for (int rr = 0; rr < 8; rr++) {
                ull a = *(const ull*)&sT[(r0v+rr)*ST + 2*kp];
                FMA2(acc[rr][0], a, w0);
                FMA2(acc[rr][1], a, w1);
                FMA2(acc[rr][2], a, w2);
                FMA2(acc[rr][3], a, w3);
            }
        }
        __syncthreads();   // all reads of sT (t) complete
#pragma unroll
        for (int rr = 0; rr < 8; rr++)
#pragma unroll
            for (int cc = 0; cc < 4; cc++) {
                float2 s = unpk2(acc[rr][cc]);
                sT[sp*4096 + (r0v+rr)*64 + cg + 16*cc] = s.x + s.y;
            }
    }
    __syncthreads();
#pragma unroll
    for (int i = 0; i < 8; i++) {
        int e = tid + i*512;
        int r = e >> 6, col = e & 63;
        float sim = sT[e] + sT[4096+e] + sT[8192+e] + sT[12288+e] + sBa2[col];
        sH[r*HPD + col] = sim;
    }
    __syncthreads();

    // ---- Phase 5: softmax over 64 channels per row (4 threads/row) ----
    if (tid < 256) {
        int row = tid >> 2, q = tid & 3;
        float* hrow = &sH[row*HPD + q*16];
        float mx = -3.4e38f;
#pragma unroll
        for (int i = 0; i < 16; i++) mx = fmaxf(mx, hrow[i]);
        mx = fmaxf(mx, __shfl_xor_sync(0xffffffffu, mx, 1));
        mx = fmaxf(mx, __shfl_xor_sync(0xffffffffu, mx, 2));
        float ev[16];
        float s = 0.f;
#pragma unroll
        for (int i = 0; i < 16; i++) { ev[i] = __expf(hrow[i] - mx); s += ev[i]; }
        s += __shfl_xor_sync(0xffffffffu, s, 1);
        s += __shfl_xor_sync(0xffffffffu, s, 2);
        float inv = 1.f / s;
#pragma unroll
        for (int i = 0; i < 16; i++) hrow[i] = ev[i] * inv;
    }
    __syncthreads();

    // ---- Phase 6: per-point channel norm over 16 neighbors + aggregate ----
    if (tid < 256) {
        int pl = tid >> 6, cc = tid & 63;
        float a[16];
        float s2 = 0.f;
#pragma unroll
        for (int j = 0; j < 16; j++) {
            a[j] = sH[(pl*16 + j)*HPD + cc];
            s2 += a[j]*a[j];
        }
        float inv = 1.f / fmaxf(sqrtf(s2), 1e-12f);
        float agg = 0.f;
#pragma unroll
        for (int j = 0; j < 16; j++)
            agg += a[j] * sVN[(pl*16 + j)*64 + cc];
        sAgg[pl*64 + cc] = agg * inv;
    }
    __syncthreads();

    // ---- Phase 7: out = agg @ w_out + b_out (2 points per thread) ----
    {
        int colc = tid & 255, pg = tid >> 8;
        float bb = b_out[colc];
        float acc0 = bb, acc1 = bb;
#pragma unroll 4
        for (int c = 0; c < 64; c++) {
            float wv = w_out[c*256 + colc];
            acc0 += sAgg[(2*pg+0)*64 + c] * wv;
            acc1 += sAgg[(2*pg+1)*64 + c] * wv;
        }
        out[(gp0 + 2*pg + 0)*256 + colc] = acc0;
        out[(gp0 + 2*pg + 1)*256 + colc] = acc1;
    }
}

// ---------------------------------------------------------------------------
extern "C" void kernel_launch(void* const* d_in, const int* in_sizes, int n_in,
                              void* d_out, int out_size)
{
    const float* x      = (const float*)d_in[0];
    const float* pos    = (const float*)d_in[1];
    const float* w_qkv  = (const float*)d_in[2];
    const float* w_pos1 = (const float*)d_in[3];
    const float* b_pos1 = (const float*)d_in[4];
    const float* w_pos2 = (const float*)d_in[5];
    const float* b_pos2 = (const float*)d_in[6];
    const float* w_att1 = (const float*)d_in[7];
    const float* b_att1 = (const float*)d_in[8];
    const float* w_att2 = (const float*)d_in[9];
    const float* b_att2 = (const float*)d_in[10];
    const float* w_out  = (const float*)d_in[11];
    const float* b_out  = (const float*)d_in[12];
    float* out = (float*)d_out;

    (void)in_sizes; (void)n_in; (void)out_size;

    const int smem_fused = SMEM_FUSED_FLOATS * 4;
    cudaFuncSetAttribute(fused_kernel,
                         cudaFuncAttributeMaxDynamicSharedMemorySize, smem_fused);

    prep_kernel<<<168, 256>>>(w_qkv, w_att1, w_att2, w_pos2);
    qkv_kernel<<<NPTS_/32, 256>>>(x);
    knn_kernel<<<B_*8, 256>>>(pos);
    fused_kernel<<<NPTS_/4, 512, smem_fused>>>(
        pos, w_pos1, b_pos1, b_pos2, b_att1, b_att2, w_out, b_out, out);
}

// round 5
// speedup vs baseline: 1.7805x; 1.1395x over previous
#include <cuda_runtime.h>

#define B_    8
#define N_    2048
#define EMB_  256
#define INNER_ 64
#define KNN_  16
#define NPTS_ (B_*N_)
#define MS    66    // mid row stride
#define HPD   68    // h/sim row stride
#define ST    260   // t row stride

typedef unsigned long long ull;

__device__ __forceinline__ float2 unpk2(ull v) {
    float2 r; asm("mov.b64 {%0,%1}, %2;" : "=f"(r.x), "=f"(r.y) : "l"(v)); return r;
}
#define FMA2(acc, a, b) asm("fma.rn.f32x2 %0, %1, %2, %0;" : "+l"(acc) : "l"(a), "l"(b))

// Scratch (device globals; no dynamic allocation allowed)
__device__ float g_qmk[NPTS_*INNER_];
__device__ float g_v  [NPTS_*INNER_];
__device__ int   g_idx[NPTS_*KNN_];
// pre-paired weights: pair p holds {w[2p][c], w[2p+1][c]}
__device__ __align__(16) float2 g_wqp[128*192];   // w_qkv
__device__ __align__(16) float2 g_w1p[32*256];    // w_att1
__device__ __align__(16) float2 g_w2p[128*64];    // w_att2
__device__ __align__(16) float2 g_wpp[32*64];     // w_pos2

// ---------------------------------------------------------------------------
__global__ __launch_bounds__(256) void prep_kernel(
    const float* __restrict__ wq, const float* __restrict__ w1,
    const float* __restrict__ w2, const float* __restrict__ wp)
{
    int i = blockIdx.x*256 + threadIdx.x;
    if (i < 24576) {
        int kp = i/192, c = i%192;
        g_wqp[i] = make_float2(wq[(2*kp)*192+c], wq[(2*kp+1)*192+c]);
    } else if (i < 32768) {
        int j = i - 24576; int kp = j>>8, c = j&255;
        g_w1p[j] = make_float2(w1[(2*kp)*256+c], w1[(2*kp+1)*256+c]);
    } else if (i < 40960) {
        int j = i - 32768; int kp = j>>6, c = j&63;
        g_w2p[j] = make_float2(w2[(2*kp)*64+c], w2[(2*kp+1)*64+c]);
    } else if (i < 43008) {
        int j = i - 40960; int kp = j>>6, c = j&63;
        g_wpp[j] = make_float2(wp[(2*kp)*64+c], wp[(2*kp+1)*64+c]);
    }
}

// ---------------------------------------------------------------------------
// qkv: 32 rows/block, 256 threads; thread tile = 8 rows x {q,k,v} of col cg.
// ---------------------------------------------------------------------------
__global__ __launch_bounds__(256) void qkv_kernel(const float* __restrict__ x)
{
    __shared__ float sx[32*EMB_];     // 32 KB
    int r0 = blockIdx.x * 32;
    {
        const float4* xin = (const float4*)(x + (size_t)r0*EMB_);
        float4* sx4 = (float4*)sx;
        for (int i = threadIdx.x; i < 2048; i += 256) sx4[i] = xin[i];
    }
    __syncthreads();

    int cg = threadIdx.x & 63, rg = threadIdx.x >> 6;   // rg 0..3 -> 8 rows
    ull acc[8][3];
#pragma unroll
    for (int rr = 0; rr < 8; rr++)
#pragma unroll
        for (int cc = 0; cc < 3; cc++) acc[rr][cc] = 0ull;

    ull wc[3], wn[3];
#pragma unroll
    for (int cc = 0; cc < 3; cc++)
        wc[cc] = *(const ull*)&g_wqp[cg + 64*cc];

    for (int kp = 0; kp < 128; kp++) {
        if (kp < 127) {
#pragma unroll
            for (int cc = 0; cc < 3; cc++)
                wn[cc] = *(const ull*)&g_wqp[(kp+1)*192 + cg + 64*cc];
        }
#pragma unroll
        for (int rr = 0; rr < 8; rr++) {
            ull a = *(const ull*)&sx[(rg*8+rr)*EMB_ + 2*kp];
            FMA2(acc[rr][0], a, wc[0]);
            FMA2(acc[rr][1], a, wc[1]);
            FMA2(acc[rr][2], a, wc[2]);
        }
#pragma unroll
        for (int cc = 0; cc < 3; cc++) wc[cc] = wn[cc];
    }
#pragma unroll
    for (int rr = 0; rr < 8; rr++) {
        float2 sq = unpk2(acc[rr][0]);
        float2 sk = unpk2(acc[rr][1]);
        float2 sv = unpk2(acc[rr][2]);
        int row = r0 + rg*8 + rr;
        g_qmk[row*64 + cg] = (sq.x + sq.y) - (sk.x + sk.y);
        g_v  [row*64 + cg] = sv.x + sv.y;
    }
}

// ---------------------------------------------------------------------------
// kNN: 256 blocks x 256 threads; 64 queries/block, 4 threads/query scanning
// 512 candidates each; 4-way merge of sorted top-16 lists.
// dynamic smem: sp[6144] + sd[4096] + si[4096 ints] = 56 KB
// ---------------------------------------------------------------------------
__global__ __launch_bounds__(256) void knn_kernel(const float* __restrict__ pos)
{
    extern __shared__ float ksm[];
    float* sp = ksm;               // 6144
    float* sd = ksm + 6144;        // 4096
    int*   si = (int*)(ksm + 10240); // 4096

    int batch = blockIdx.x >> 5;
    int chunk = blockIdx.x & 31;
    const float* pb = pos + batch*N_*3;
    for (int e = threadIdx.x; e < N_*3; e += 256) sp[e] = pb[e];
    __syncthreads();

    int q = threadIdx.x >> 2;          // 0..63 local query
    int s = threadIdx.x & 3;           // shard
    int qi = chunk*64 + q;
    float px = sp[qi*3+0], py = sp[qi*3+1], pz = sp[qi*3+2];

    float bd[KNN_]; int bi[KNN_];
#pragma unroll
    for (int t = 0; t < KNN_; t++) { bd[t] = 3.4e38f; bi[t] = 0; }

    int j0 = s * 512;
    for (int j = j0; j < j0 + 512; j++) {
        float dx = sp[j*3+0]-px, dy = sp[j*3+1]-py, dz = sp[j*3+2]-pz;
        float d2 = dx*dx + dy*dy + dz*dz;
        if (d2 < bd[KNN_-1]) {
            float cd = d2; int ci = j;
#pragma unroll
            for (int t = 0; t < KNN_; t++) {
                if (cd < bd[t]) {
                    float td = bd[t]; bd[t] = cd; cd = td;
                    int   ti = bi[t]; bi[t] = ci; ci = ti;
                }
            }
        }
    }
    int lb = (q*4 + s)*16;
#pragma unroll
    for (int t = 0; t < KNN_; t++) { sd[lb+t] = bd[t]; si[lb+t] = bi[t]; }
    __syncthreads();

    if (threadIdx.x < 64) {
        int qq = threadIdx.x;
        int p[4] = {0,0,0,0};
        int base = qq*64;
        int obase = (batch*N_ + chunk*64 + qq)*KNN_;
#pragma unroll
        for (int t = 0; t < KNN_; t++) {
            float best = sd[base + 0*16 + p[0]]; int bsel = 0;
            float c1 = sd[base + 1*16 + p[1]];
            if (c1 < best) { best = c1; bsel = 1; }
            float c2 = sd[base + 2*16 + p[2]];
            if (c2 < best) { best = c2; bsel = 2; }
            float c3 = sd[base + 3*16 + p[3]];
            if (c3 < best) { best = c3; bsel = 3; }
            g_idx[obase + t] = batch*N_ + si[base + bsel*16 + p[bsel]];
            p[bsel]++;
        }
    }
}

// ---------------------------------------------------------------------------
// Fused kernel: 2 points (32 pairs) per block, 256 threads, 2 CTAs/SM.
// ---------------------------------------------------------------------------
#define SMEM_FUSED_FLOATS 17568

__global__ __launch_bounds__(256, 2) void fused_kernel(
    const float* __restrict__ pos,
    const float* __restrict__ w_pos1, const float* __restrict__ b_pos1,
    const float* __restrict__ b_pos2,
    const float* __restrict__ b_att1, const float* __restrict__ b_att2,
    const float* __restrict__ w_out,  const float* __restrict__ b_out,
    float* __restrict__ out)
{
    extern __shared__ float sm[];
    float* sT   = sm;                    // 8320: mid(stride 66) -> t(stride 260) -> partials(8192)
    float* sH   = sm + 8320;             // 2176 (stride 68)
    float* sVN  = sm + 10496;            // 2048
    float* sWPp = sm + 12544;            // 4096 (float2 pairs)
    float* sRel = sm + 16640;            // 128
    float* sAgg = sRel + 128;            // 128
    float* sWP1 = sAgg + 128;            // 192
    float* sBp1 = sWP1 + 192;            // 64
    float* sBp2 = sBp1 + 64;             // 64
    float* sBa1 = sBp2 + 64;             // 256
    float* sBa2 = sBa1 + 256;            // 64
    int*   sNbr = (int*)(sBa2 + 64);     // 32

    const int tid = threadIdx.x;
    const int gp0 = blockIdx.x * 2;

    // ---- Phase 0: stage wp2 + biases + neighbor rel-pos ----
    {
        float4* d2 = (float4*)sWPp;  const float4* s2 = (const float4*)g_wpp;
        for (int i = tid; i < 1024; i += 256) d2[i] = s2[i];
    }
    if (tid < 192) sWP1[tid] = w_pos1[tid];
    if (tid < 64) {
        sBp1[tid] = b_pos1[tid];
        sBp2[tid] = b_pos2[tid];
        sBa2[tid] = b_att2[tid];
    }
    sBa1[tid] = b_att1[tid];   // all 256 threads: full coverage
    if (tid < 32) {
        int pl = tid >> 4;
        int gp = gp0 + pl;
        int nbr = g_idx[gp*KNN_ + (tid & 15)];
        sNbr[tid] = nbr;
        sRel[tid*4+0] = pos[nbr*3+0] - pos[gp*3+0];
        sRel[tid*4+1] = pos[nbr*3+1] - pos[gp*3+1];
        sRel[tid*4+2] = pos[nbr*3+2] - pos[gp*3+2];
    }
    __syncthreads();

    // ---- Phase 1: mid = relu(rel @ wp1 + bp1) -> sT stride MS (32x64) ----
#pragma unroll
    for (int i = 0; i < 8; i++) {
        int e = tid + i*256;
        int r = e >> 6, c = e & 63;
        float a = sRel[r*4+0]*sWP1[c] + sRel[r*4+1]*sWP1[64+c]
                + sRel[r*4+2]*sWP1[128+c] + sBp1[c];
        sT[r*MS + c] = fmaxf(a, 0.f);
    }
    __syncthreads();

    // ---- Phase 2: rpe = mid @ wp2 + bp2; h = qmk[nbr]+rpe; vn = v[nbr]+rpe ----
    {
        int cg = tid & 31, rg = tid >> 5;   // rg 0..7 -> 4 rows
        int r0v = rg * 4;
        ull acc[4][2];
#pragma unroll
        for (int rr = 0; rr < 4; rr++) { acc[rr][0] = 0ull; acc[rr][1] = 0ull; }
#pragma unroll 4
        for (int kp = 0; kp < 32; kp++) {
            ull w0 = *(const ull*)&sWPp[(kp*64 + cg)*2];
            ull w1 = *(const ull*)&sWPp[(kp*64 + cg + 32)*2];
#pragma unroll
            for (int rr = 0; rr < 4; rr++) {
                ull a = *(const ull*)&sT[(r0v+rr)*MS + 2*kp];
                FMA2(acc[rr][0], a, w0);
                FMA2(acc[rr][1], a, w1);
            }
        }
#pragma unroll
        for (int rr = 0; rr < 4; rr++) {
            int r = r0v + rr;
            int nbr = sNbr[r];
#pragma unroll
            for (int cc = 0; cc < 2; cc++) {
                int col = cg + 32*cc;
                float2 s = unpk2(acc[rr][cc]);
                float rpe = s.x + s.y + sBp2[col];
                sH [r*HPD + col] = g_qmk[nbr*64 + col] + rpe;
                sVN[r*64  + col] = g_v  [nbr*64 + col] + rpe;
            }
        }
    }
    __syncthreads();

    // ---- Phase 3: t = relu(h @ w_att1 + b_att1) -> sT stride ST (32x256) ----
    {
        int cg = tid & 63, rg = tid >> 6;   // rg 0..3 -> 8 rows
        int r0v = rg * 8;
        ull acc[8][4];
#pragma unroll
        for (int rr = 0; rr < 8; rr++)
#pragma unroll
            for (int cc = 0; cc < 4; cc++) acc[rr][cc] = 0ull;

        ull wc[4], wn[4];
#pragma unroll
        for (int cc = 0; cc < 4; cc++)
            wc[cc] = *(const ull*)&g_w1p[cg + 64*cc];

        for (int kp = 0; kp < 32; kp++) {
            if (kp < 31) {
#pragma unroll
                for (int cc = 0; cc < 4; cc++)
                    wn[cc] = *(const ull*)&g_w1p[(kp+1)*256 + cg + 64*cc];
            }
#pragma unroll
            for (int rr = 0; rr < 8; rr++) {
                ull a = *(const ull*)&sH[(r0v+rr)*HPD + 2*kp];
                FMA2(acc[rr][0], a, wc[0]);
                FMA2(acc[rr][1], a, wc[1]);
                FMA2(acc[rr][2], a, wc[2]);
                FMA2(acc[rr][3], a, wc[3]);
            }
#pragma unroll
            for (int cc = 0; cc < 4; cc++) wc[cc] = wn[cc];
        }
#pragma unroll
        for (int rr = 0; rr < 8; rr++)
#pragma unroll
            for (int cc = 0; cc < 4; cc++) {
                int col = cg + 64*cc;
                float2 s = unpk2(acc[rr][cc]);
                sT[(r0v+rr)*ST + col] = fmaxf(s.x + s.y + sBa1[col], 0.f);
            }
    }
    __syncthreads();

    // ---- Phase 4: sim = t @ w_att2 + b_att2 (split-K x4, w2 from L2) -> sH ----
    {
        int sp = tid >> 6;                 // 0..3 k-split
        int t  = tid & 63;
        int cg = t & 15, rg = t >> 4;      // rg 0..3 -> 8 rows
        int r0v = rg * 8;
        ull acc[8][4];
#pragma unroll
        for (int rr = 0; rr < 8; rr++)
#pragma unroll
            for (int cc = 0; cc < 4; cc++) acc[rr][cc] = 0ull;

        int kbase = sp * 32;
        ull wc[4], wn[4];
#pragma unroll
        for (int cc = 0; cc < 4; cc++)
            wc[cc] = *(const ull*)&g_w2p[kbase*64 + cg + 16*cc];

        for (int j = 0; j < 32; j++) {
            int kp = kbase + j;
            if (j < 31) {
#pragma unroll
                for (int cc = 0; cc < 4; cc++)
                    wn[cc] = *(const ull*)&g_w2p[(kp+1)*64 + cg + 16*cc];
            }
#pragma unroll
            for (int rr = 0; rr < 8; rr++) {
                ull a = *(const ull*)&sT[(r0v+rr)*ST + 2*kp];
                FMA2(acc[rr][0], a, wc[0]);
                FMA2(acc[rr][1], a, wc[1]);
                FMA2(acc[rr][2], a, wc[2]);
                FMA2(acc[rr][3], a, wc[3]);
            }
#pragma unroll
            for (int cc = 0; cc < 4; cc++) wc[cc] = wn[cc];
        }
        __syncthreads();   // all reads of sT (t) complete
#pragma unroll
        for (int rr = 0; rr < 8; rr++)
#pragma unroll
            for (int cc = 0; cc < 4; cc++) {
                float2 s = unpk2(acc[rr][cc]);
                sT[sp*2048 + (r0v+rr)*64 + cg + 16*cc] = s.x + s.y;
            }
    }
    __syncthreads();
#pragma unroll
    for (int i = 0; i < 8; i++) {
        int e = tid + i*256;
        int r = e >> 6, col = e & 63;
        float sim = sT[e] + sT[2048+e] + sT[4096+e] + sT[6144+e] + sBa2[col];
        sH[r*HPD + col] = sim;
    }
    __syncthreads();

    // ---- Phase 5: softmax over 64 channels per row (4 threads/row) ----
    if (tid < 128) {
        int row = tid >> 2, q = tid & 3;
        float* hrow = &sH[row*HPD + q*16];
        float mx = -3.4e38f;
#pragma unroll
        for (int i = 0; i < 16; i++) mx = fmaxf(mx, hrow[i]);
        mx = fmaxf(mx, __shfl_xor_sync(0xffffffffu, mx, 1));
        mx = fmaxf(mx, __shfl_xor_sync(0xffffffffu, mx, 2));
        float ev[16];
        float s = 0.f;
#pragma unroll
        for (int i = 0; i < 16; i++) { ev[i] = __expf(hrow[i] - mx); s += ev[i]; }
        s += __shfl_xor_sync(0xffffffffu, s, 1);
        s += __shfl_xor_sync(0xffffffffu, s, 2);
        float inv = 1.f / s;
#pragma unroll
        for (int i = 0; i < 16; i++) hrow[i] = ev[i] * inv;
    }
    __syncthreads();

    // ---- Phase 6: per-point channel norm over 16 neighbors + aggregate ----
    if (tid < 128) {
        int pl = tid >> 6, cc = tid & 63;
        float a[16];
        float s2 = 0.f;
#pragma unroll
        for (int j = 0; j < 16; j++) {
            a[j] = sH[(pl*16 + j)*HPD + cc];
            s2 += a[j]*a[j];
        }
        float inv = 1.f / fmaxf(sqrtf(s2), 1e-12f);
        float agg = 0.f;
#pragma unroll
        for (int j = 0; j < 16; j++)
            agg += a[j] * sVN[(pl*16 + j)*64 + cc];
        sAgg[pl*64 + cc] = agg * inv;
    }
    __syncthreads();

    // ---- Phase 7: out = agg @ w_out + b_out (both points per thread) ----
    {
        float bb = b_out[tid];
        float acc0 = bb, acc1 = bb;
#pragma unroll 4
        for (int c = 0; c < 64; c++) {
            float wv = w_out[c*256 + tid];
            acc0 += sAgg[c]      * wv;
            acc1 += sAgg[64 + c] * wv;
        }
        out[(gp0 + 0)*256 + tid] = acc0;
        out[(gp0 + 1)*256 + tid] = acc1;
    }
}

// ---------------------------------------------------------------------------
extern "C" void kernel_launch(void* const* d_in, const int* in_sizes, int n_in,
                              void* d_out, int out_size)
{
    const float* x      = (const float*)d_in[0];
    const float* pos    = (const float*)d_in[1];
    const float* w_qkv  = (const float*)d_in[2];
    const float* w_pos1 = (const float*)d_in[3];
    const float* b_pos1 = (const float*)d_in[4];
    const float* w_pos2 = (const float*)d_in[5];
    const float* b_pos2 = (const float*)d_in[6];
    const float* w_att1 = (const float*)d_in[7];
    const float* b_att1 = (const float*)d_in[8];
    const float* w_att2 = (const float*)d_in[9];
    const float* b_att2 = (const float*)d_in[10];
    const float* w_out  = (const float*)d_in[11];
    const float* b_out  = (const float*)d_in[12];
    float* out = (float*)d_out;

    (void)in_sizes; (void)n_in; (void)out_size;

    const int smem_fused = SMEM_FUSED_FLOATS * 4;
    cudaFuncSetAttribute(fused_kernel,
                         cudaFuncAttributeMaxDynamicSharedMemorySize, smem_fused);
    const int smem_knn = (6144 + 4096 + 4096) * 4;
    cudaFuncSetAttribute(knn_kernel,
                         cudaFuncAttributeMaxDynamicSharedMemorySize, smem_knn);

    prep_kernel<<<168, 256>>>(w_qkv, w_att1, w_att2, w_pos2);
    qkv_kernel<<<NPTS_/32, 256>>>(x);
    knn_kernel<<<256, 256, smem_knn>>>(pos);
    fused_kernel<<<NPTS_/2, 256, smem_fused>>>(
        pos, w_pos1, b_pos1, b_pos2, b_att1, b_att2, w_out, b_out, out);
}